// round 3
// baseline (speedup 1.0000x reference)
#include <cuda_runtime.h>

// B=64, T=1024, J=32 (fixed by the reference's setup_inputs)
#define B_ 64
#define T_ 1024
#define J_ 32

// Scratch: per-(b,t) root trajectory (x,z only) — 64*1024 float2 = 512 KB
__device__ float2 d_traj[B_ * T_];

// Rotate point p by quaternion (w, x, y, z): p' = p + 2w(v x p) + 2 v x (v x p)
__device__ __forceinline__ void quat_rotate(
    float w, float x, float y, float z,
    float px, float py, float pz,
    float& rx, float& ry, float& rz)
{
    float tx = 2.0f * (y * pz - z * py);
    float ty = 2.0f * (z * px - x * pz);
    float tz = 2.0f * (x * py - y * px);
    rx = px + w * tx + (y * tz - z * ty);
    ry = py + w * ty + (z * tx - x * tz);
    rz = pz + w * tz + (x * ty - y * tx);
}

// One block per batch b; 1024 threads = T time steps.
// Computes traj[b,t] = rotate(conj(root[b,0]), glb_pos[b,0,0]).xz
//                      + sum_{s<t} rotate(conj(root[b,s]), glb_vel[b,s,0]).xz
__global__ void traj_kernel(const float* __restrict__ glb_pos,
                            const float* __restrict__ glb_vel,
                            const float* __restrict__ root_rot)
{
    const int b = blockIdx.x;
    const int t = threadIdx.x;

    // conj(root[b,t])
    const float4 q4 = __ldg(reinterpret_cast<const float4*>(root_rot) + (size_t)b * T_ + t);
    const float w = q4.x, qx = -q4.y, qy = -q4.z, qz = -q4.w;

    // vel_rot[b,t,0] (x,z) for t < T-1
    float ex = 0.0f, ez = 0.0f;
    if (t < T_ - 1) {
        const float* v = glb_vel + (((size_t)b * (T_ - 1) + t) * J_) * 3;  // joint 0
        float px = __ldg(v + 0), py = __ldg(v + 1), pz = __ldg(v + 2);
        float rx, ry, rz;
        quat_rotate(w, qx, qy, qz, px, py, pz, rx, ry, rz);
        ex = rx; ez = rz;
    }

    // --- exclusive block scan of (ex, ez) over the 1024 threads ---
    const int lane = t & 31, warp = t >> 5;
    float ix = ex, iz = ez;  // warp-inclusive
    #pragma unroll
    for (int o = 1; o < 32; o <<= 1) {
        float sx = __shfl_up_sync(0xFFFFFFFFu, ix, o);
        float sz = __shfl_up_sync(0xFFFFFFFFu, iz, o);
        if (lane >= o) { ix += sx; iz += sz; }
    }

    __shared__ float wsx[32], wsz[32];
    __shared__ float2 base_sh;
    if (lane == 31) { wsx[warp] = ix; wsz[warp] = iz; }

    if (t == 0) {
        // base = rotate(conj(root[b,0]), glb_pos[b,0,0]); thread 0 holds root[b,0]
        const float* p = glb_pos + (size_t)b * T_ * J_ * 3;
        float bx, by, bz;
        quat_rotate(w, qx, qy, qz, __ldg(p + 0), __ldg(p + 1), __ldg(p + 2), bx, by, bz);
        base_sh = make_float2(bx, bz);
    }
    __syncthreads();

    if (warp == 0) {
        float sx = wsx[lane], sz = wsz[lane];
        #pragma unroll
        for (int o = 1; o < 32; o <<= 1) {
            float ax = __shfl_up_sync(0xFFFFFFFFu, sx, o);
            float az = __shfl_up_sync(0xFFFFFFFFu, sz, o);
            if (lane >= o) { sx += ax; sz += az; }
        }
        wsx[lane] = sx; wsz[lane] = sz;
    }
    __syncthreads();

    // exclusive prefix = (inclusive within warp - own) + sum of preceding warps
    float prefx = (ix - ex) + (warp > 0 ? wsx[warp - 1] : 0.0f);
    float prefz = (iz - ez) + (warp > 0 ? wsz[warp - 1] : 0.0f);

    d_traj[(size_t)b * T_ + t] = make_float2(base_sh.x + prefx, base_sh.y + prefz);
}

// One thread per (b,t,j). j is the fastest dim (j = idx & 31), so each warp
// shares one (b,t): the root-quat float4 load and traj float2 load broadcast.
__global__ void apply_kernel(const float* __restrict__ glb_pos,
                             const float* __restrict__ glb_rot,
                             const float* __restrict__ root_rot,
                             float* __restrict__ pos_out,
                             float* __restrict__ rot_out)
{
    const size_t idx = (size_t)blockIdx.x * blockDim.x + threadIdx.x;
    const size_t N = (size_t)B_ * T_ * J_;
    if (idx >= N) return;

    const size_t bt = idx >> 5;  // J_ = 32

    const float4 q4 = __ldg(reinterpret_cast<const float4*>(root_rot) + bt);
    const float w = q4.x, qx = -q4.y, qy = -q4.z, qz = -q4.w;

    // --- pos path ---
    const float* p = glb_pos + idx * 3;
    float px = p[0], py = p[1], pz = p[2];
    float rx, ry, rz;
    quat_rotate(w, qx, qy, qz, px, py, pz, rx, ry, rz);

    const float2 tr = __ldg(&d_traj[bt]);
    float* po = pos_out + idx * 3;
    po[0] = rx + tr.x;
    po[1] = ry;
    po[2] = rz + tr.y;

    // --- rot path: standardize(conj(root) * glb_rot) ---
    const float4 g = __ldg(reinterpret_cast<const float4*>(glb_rot) + idx);
    float mw = w * g.x - qx * g.y - qy * g.z - qz * g.w;
    float mx = w * g.y + qx * g.x + qy * g.w - qz * g.z;
    float my = w * g.z - qx * g.w + qy * g.x + qz * g.y;
    float mz = w * g.w + qx * g.z - qy * g.y + qz * g.x;
    if (mw < 0.0f) { mw = -mw; mx = -mx; my = -my; mz = -mz; }
    reinterpret_cast<float4*>(rot_out)[idx] = make_float4(mw, mx, my, mz);
}

extern "C" void kernel_launch(void* const* d_in, const int* in_sizes, int n_in,
                              void* d_out, int out_size)
{
    const float* glb_pos  = (const float*)d_in[0];  // [B,T,J,3]
    const float* glb_rot  = (const float*)d_in[1];  // [B,T,J,4]
    const float* glb_vel  = (const float*)d_in[2];  // [B,T-1,J,3]
    const float* root_rot = (const float*)d_in[3];  // [B,T,1,4]

    float* pos_out = (float*)d_out;                                  // [B,T,J,3]
    float* rot_out = (float*)d_out + (size_t)B_ * T_ * J_ * 3;       // [B,T,J,4]

    traj_kernel<<<B_, T_>>>(glb_pos, glb_vel, root_rot);

    const size_t N = (size_t)B_ * T_ * J_;
    const int threads = 256;
    const int blocks = (int)((N + threads - 1) / threads);
    apply_kernel<<<blocks, threads>>>(glb_pos, glb_rot, root_rot, pos_out, rot_out);
}